// round 2
// baseline (speedup 1.0000x reference)
#include <cuda_runtime.h>
#include <math.h>

#define HID 256
#define WPB 4            // warps (points) per block
#define TPB (WPB * 32)

__device__ double g_acc;

// ---- packed f32x2 helpers (sm_100+ PTX; FFMA2 doubles fp32 FMA throughput) ----
__device__ __forceinline__ void fma2(unsigned long long &d, unsigned long long a, unsigned long long b) {
    asm("fma.rn.f32x2 %0, %1, %2, %0;" : "+l"(d) : "l"(a), "l"(b));
}
__device__ __forceinline__ unsigned long long pack2(float x) {
    unsigned long long r;
    asm("mov.b64 %0, {%1, %1};" : "=l"(r) : "f"(x));
    return r;
}
__device__ __forceinline__ float2 unpack2(unsigned long long v) {
    float2 f;
    asm("mov.b64 {%0, %1}, %2;" : "=f"(f.x), "=f"(f.y) : "l"(v));
    return f;
}

struct State {
    float h[8];        // activation value channel
    float d[3][8];     // first directional derivatives (x,y,z)
    float s[3][8];     // second directional derivatives (x,y,z)
};

// Write this warp's state into its shared staging slice: channels [h, d0..d2, s0..s2]
__device__ __forceinline__ void store_state(float *aw, int lane, const State &st) {
    float *p = aw + (lane << 3);
    *(float4 *)(p + 0 * HID)     = make_float4(st.h[0], st.h[1], st.h[2], st.h[3]);
    *(float4 *)(p + 0 * HID + 4) = make_float4(st.h[4], st.h[5], st.h[6], st.h[7]);
#pragma unroll
    for (int i = 0; i < 3; i++) {
        *(float4 *)(p + (1 + i) * HID)     = make_float4(st.d[i][0], st.d[i][1], st.d[i][2], st.d[i][3]);
        *(float4 *)(p + (1 + i) * HID + 4) = make_float4(st.d[i][4], st.d[i][5], st.d[i][6], st.d[i][7]);
        *(float4 *)(p + (4 + i) * HID)     = make_float4(st.s[i][0], st.s[i][1], st.s[i][2], st.s[i][3]);
        *(float4 *)(p + (4 + i) * HID + 4) = make_float4(st.s[i][4], st.s[i][5], st.s[i][6], st.s[i][7]);
    }
}

// One 256->256 dense layer + tanh, propagating all 7 channels.
// aw: this warp's [7][256] shared buffer holding current channel vectors.
// Each lane owns output units j = lane*8 .. lane*8+7.
__device__ __forceinline__ void dense_layer(const float *__restrict__ W,
                                            const float *__restrict__ b,
                                            const float *__restrict__ aw,
                                            int lane, State &st) {
    unsigned long long acc[7][4];
#pragma unroll
    for (int c = 0; c < 7; c++)
#pragma unroll
        for (int t = 0; t < 4; t++) acc[c][t] = 0ull;

    const float *wp = W + (lane << 3);
#pragma unroll 2
    for (int k = 0; k < HID; k += 2) {
        const ulonglong2 *w0 = (const ulonglong2 *)(wp);
        const ulonglong2 *w1 = (const ulonglong2 *)(wp + HID);
        ulonglong2 wA0 = w0[0], wB0 = w0[1];   // row k:   j0..j3, j4..j7 (as 4 packed f32x2)
        ulonglong2 wA1 = w1[0], wB1 = w1[1];   // row k+1
#pragma unroll
        for (int c = 0; c < 7; c++) {
            float2 av = *(const float2 *)(aw + c * HID + k);   // broadcast LDS.64
            unsigned long long a0 = pack2(av.x);
            unsigned long long a1 = pack2(av.y);
            fma2(acc[c][0], a0, wA0.x);
            fma2(acc[c][1], a0, wA0.y);
            fma2(acc[c][2], a0, wB0.x);
            fma2(acc[c][3], a0, wB0.y);
            fma2(acc[c][0], a1, wA1.x);
            fma2(acc[c][1], a1, wA1.y);
            fma2(acc[c][2], a1, wB1.x);
            fma2(acc[c][3], a1, wB1.y);
        }
        wp += 2 * HID;
    }

    // bias for the value channel
    float4 bA = *(const float4 *)(b + (lane << 3));
    float4 bB = *(const float4 *)(b + (lane << 3) + 4);
    float bb[8] = {bA.x, bA.y, bA.z, bA.w, bB.x, bB.y, bB.z, bB.w};

#pragma unroll
    for (int t = 0; t < 4; t++) {
        float2 zv  = unpack2(acc[0][t]);
        float2 zd0 = unpack2(acc[1][t]);
        float2 zd1 = unpack2(acc[2][t]);
        float2 zd2 = unpack2(acc[3][t]);
        float2 zs0 = unpack2(acc[4][t]);
        float2 zs1 = unpack2(acc[5][t]);
        float2 zs2 = unpack2(acc[6][t]);
        {
            int r = 2 * t;
            float y = tanhf(zv.x + bb[r]);
            float g = 1.f - y * y;
            float tg = 2.f * y * g;
            st.h[r] = y;
            st.d[0][r] = g * zd0.x; st.d[1][r] = g * zd1.x; st.d[2][r] = g * zd2.x;
            st.s[0][r] = g * zs0.x - tg * zd0.x * zd0.x;
            st.s[1][r] = g * zs1.x - tg * zd1.x * zd1.x;
            st.s[2][r] = g * zs2.x - tg * zd2.x * zd2.x;
        }
        {
            int r = 2 * t + 1;
            float y = tanhf(zv.y + bb[r]);
            float g = 1.f - y * y;
            float tg = 2.f * y * g;
            st.h[r] = y;
            st.d[0][r] = g * zd0.y; st.d[1][r] = g * zd1.y; st.d[2][r] = g * zd2.y;
            st.s[0][r] = g * zs0.y - tg * zd0.y * zd0.y;
            st.s[1][r] = g * zs1.y - tg * zd1.y * zd1.y;
            st.s[2][r] = g * zs2.y - tg * zd2.y * zd2.y;
        }
    }
}

__global__ void __launch_bounds__(TPB) helm_kernel(
    const float *__restrict__ inputs,
    const float *__restrict__ W1, const float *__restrict__ b1,
    const float *__restrict__ W2, const float *__restrict__ b2,
    const float *__restrict__ W3, const float *__restrict__ b3,
    const float *__restrict__ W4, const float *__restrict__ b4,
    int n, float k2) {
    __shared__ float a_sh[WPB][7][HID];
    __shared__ double red[WPB];

    int lane = threadIdx.x & 31;
    int w = threadIdx.x >> 5;
    int pt = blockIdx.x * WPB + w;

    if (pt < n) {
        float p0 = inputs[pt * 3 + 0];
        float p1 = inputs[pt * 3 + 1];
        float p2 = inputs[pt * 3 + 2];

        State st;
        // ---- Layer 1: 3 -> 256.  dz_i = W1[i,:], d2z_i = 0 ----
        float wv[3][8];
#pragma unroll
        for (int i = 0; i < 3; i++) {
            float4 a = *(const float4 *)(W1 + i * HID + (lane << 3));
            float4 c = *(const float4 *)(W1 + i * HID + (lane << 3) + 4);
            wv[i][0] = a.x; wv[i][1] = a.y; wv[i][2] = a.z; wv[i][3] = a.w;
            wv[i][4] = c.x; wv[i][5] = c.y; wv[i][6] = c.z; wv[i][7] = c.w;
        }
        float4 bA = *(const float4 *)(b1 + (lane << 3));
        float4 bB = *(const float4 *)(b1 + (lane << 3) + 4);
        float bb[8] = {bA.x, bA.y, bA.z, bA.w, bB.x, bB.y, bB.z, bB.w};
#pragma unroll
        for (int r = 0; r < 8; r++) {
            float z = p0 * wv[0][r] + p1 * wv[1][r] + p2 * wv[2][r] + bb[r];
            float y = tanhf(z);
            float g = 1.f - y * y;
            float tg = 2.f * y * g;
            st.h[r] = y;
#pragma unroll
            for (int i = 0; i < 3; i++) {
                st.d[i][r] = g * wv[i][r];
                st.s[i][r] = -tg * wv[i][r] * wv[i][r];
            }
        }

        float *aw = &a_sh[w][0][0];
        store_state(aw, lane, st);
        __syncwarp();

        // ---- Layer 2 ----
        dense_layer(W2, b2, aw, lane, st);
        __syncwarp();
        store_state(aw, lane, st);
        __syncwarp();

        // ---- Layer 3 ----
        dense_layer(W3, b3, aw, lane, st);

        // ---- Layer 4: 256 -> 1, value + Laplacian ----
        float4 w4a = *(const float4 *)(W4 + (lane << 3));
        float4 w4b = *(const float4 *)(W4 + (lane << 3) + 4);
        float wv4[8] = {w4a.x, w4a.y, w4a.z, w4a.w, w4b.x, w4b.y, w4b.z, w4b.w};
        float su = 0.f, sl = 0.f;
#pragma unroll
        for (int r = 0; r < 8; r++) {
            su += st.h[r] * wv4[r];
            sl += (st.s[0][r] + st.s[1][r] + st.s[2][r]) * wv4[r];
        }
#pragma unroll
        for (int off = 16; off > 0; off >>= 1) {
            su += __shfl_xor_sync(0xFFFFFFFFu, su, off);
            sl += __shfl_xor_sync(0xFFFFFFFFu, sl, off);
        }
        if (lane == 0) {
            float u = su + b4[0];
            float resid = sl + k2 * u;
            red[w] = (double)resid * (double)resid;
        }
    } else if (lane == 0) {
        red[w] = 0.0;
    }

    __syncthreads();
    if (threadIdx.x == 0) {
        double t = 0.0;
#pragma unroll
        for (int i = 0; i < WPB; i++) t += red[i];
        atomicAdd(&g_acc, t);
    }
}

__global__ void k_zero() { g_acc = 0.0; }

__global__ void k_fin(float *out, double inv_n) {
    out[0] = (float)(g_acc * inv_n);
}

extern "C" void kernel_launch(void *const *d_in, const int *in_sizes, int n_in,
                              void *d_out, int out_size) {
    const float *inputs = (const float *)d_in[0];
    const float *W1 = (const float *)d_in[1];
    const float *b1 = (const float *)d_in[2];
    const float *W2 = (const float *)d_in[3];
    const float *b2 = (const float *)d_in[4];
    const float *W3 = (const float *)d_in[5];
    const float *b3 = (const float *)d_in[6];
    const float *W4 = (const float *)d_in[7];
    const float *b4 = (const float *)d_in[8];

    int n = in_sizes[0] / 3;
    const double C = 343.0;
    const double OMEGA = 2.0 * 3.14159265358979323846 * 1000.0;
    float k2 = (float)((C / OMEGA) * (C / OMEGA));

    int blocks = (n + WPB - 1) / WPB;
    k_zero<<<1, 1>>>();
    helm_kernel<<<blocks, TPB>>>(inputs, W1, b1, W2, b2, W3, b3, W4, b4, n, k2);
    k_fin<<<1, 1>>>((float *)d_out, 1.0 / (double)n);
}

// round 8
// speedup vs baseline: 1.8831x; 1.8831x over previous
#include <cuda_runtime.h>
#include <cuda_bf16.h>
#include <math.h>
#include <stdint.h>

#define HID    256
#define PTS    16
#define THREADS 256
#define STRB   528                 // activation row stride in bytes (132 words = 4 banks/row)
#define PLANE  (PTS * STRB)        // 8448 B per (ch,split) plane
#define ACT_BYTES (14 * PLANE)     // 7 channels x {hi,lo} = 118272
#define OFF_RED   ACT_BYTES
#define OFF_INP   (OFF_RED + 128)
#define SMEM_ALLOC (OFF_INP + 256)

__device__ double g_acc;
// Fragment-native A images: [layer][split][jt][ks][lane] -> uint4 (a0..a3)
__device__ uint4 g_aimg[2 * 2 * 16 * 16 * 32];

static __device__ __host__ __forceinline__ int aidx(int layer, int split, int jt, int ks, int lane) {
    return ((((layer * 2 + split) * 16 + jt) * 16 + ks) * 32) + lane;
}

__device__ __forceinline__ void mma_bf16(float* d, const uint32_t* a, const uint32_t* b) {
    asm volatile(
        "mma.sync.aligned.m16n8k16.row.col.f32.bf16.bf16.f32 "
        "{%0,%1,%2,%3},{%4,%5,%6,%7},{%8,%9},{%0,%1,%2,%3};"
        : "+f"(d[0]), "+f"(d[1]), "+f"(d[2]), "+f"(d[3])
        : "r"(a[0]), "r"(a[1]), "r"(a[2]), "r"(a[3]), "r"(b[0]), "r"(b[1]));
}

// store hi/lo bf16 split of v at (point p, k) of channel ch
__device__ __forceinline__ void split_store(char* act, int ch, int p, int k, float v) {
    __nv_bfloat16 hi = __float2bfloat16(v);
    __nv_bfloat16 lo = __float2bfloat16(v - __bfloat162float(hi));
    char* base = act + ch * 2 * PLANE + p * STRB + k * 2;
    *(unsigned short*)(base)         = *(unsigned short*)&hi;
    *(unsigned short*)(base + PLANE) = *(unsigned short*)&lo;
}

// ============ prep: W2/W3 -> bf16 hi/lo mma A-fragment images ============
__global__ void prep_kernel(const float* __restrict__ W2, const float* __restrict__ W3) {
    int e = blockIdx.x * blockDim.x + threadIdx.x;
    if (e >= 2 * 2 * 16 * 16 * 32) return;
    int lane = e & 31, ks = (e >> 5) & 15, jt = (e >> 9) & 15;
    int split = (e >> 13) & 1, layer = (e >> 14) & 1;
    const float* W = layer ? W3 : W2;
    int gid = lane >> 2, tig = lane & 3;
    uint32_t regs[4];
#pragma unroll
    for (int r = 0; r < 4; r++) {
        int j = jt * 16 + gid + ((r & 1) << 3);       // a0/a2: row gid, a1/a3: row gid+8
        int k = ks * 16 + tig * 2 + ((r >> 1) << 3);  // a0/a1: k lo, a2/a3: k+8
        float w0 = W[k * HID + j];
        float w1 = W[(k + 1) * HID + j];
        __nv_bfloat16 h0, h1;
        if (split == 0) {
            h0 = __float2bfloat16(w0);
            h1 = __float2bfloat16(w1);
        } else {
            __nv_bfloat16 t0 = __float2bfloat16(w0), t1 = __float2bfloat16(w1);
            h0 = __float2bfloat16(w0 - __bfloat162float(t0));
            h1 = __float2bfloat16(w1 - __bfloat162float(t1));
        }
        regs[r] = (uint32_t)*(unsigned short*)&h0 | ((uint32_t)*(unsigned short*)&h1 << 16);
    }
    g_aimg[e] = make_uint4(regs[0], regs[1], regs[2], regs[3]);
}

// ============ main kernel ============
__global__ void __launch_bounds__(THREADS, 1) helm_hmma(
    const float* __restrict__ inputs,
    const float* __restrict__ W1, const float* __restrict__ b1,
    const float* __restrict__ b2, const float* __restrict__ b3,
    const float* __restrict__ W4, const float* __restrict__ b4,
    int n, float k2) {

    extern __shared__ char smem[];
    char* act = smem;
    float* red = (float*)(smem + OFF_RED);   // [16] u, [16] l
    float* inp = (float*)(smem + OFF_INP);   // [16][3]

    int tid = threadIdx.x, wid = tid >> 5, lane = tid & 31;
    int gid = lane >> 2, tig = lane & 3;
    int pt0 = blockIdx.x * PTS;

    if (tid < 32) red[tid] = 0.f;
    if (tid < PTS * 3) {
        int p = tid / 3, c = tid % 3;
        inp[tid] = (pt0 + p < n) ? inputs[(pt0 + p) * 3 + c] : 0.f;
    }
    __syncthreads();

    // ---- Layer 1 (3 -> 256): thread = output unit j ----
    {
        int j = tid;
        float w0 = W1[j], w1 = W1[HID + j], w2 = W1[2 * HID + j], bb = b1[j];
#pragma unroll 4
        for (int p = 0; p < PTS; p++) {
            float x0 = inp[p * 3 + 0], x1 = inp[p * 3 + 1], x2 = inp[p * 3 + 2];
            float z = fmaf(x0, w0, fmaf(x1, w1, fmaf(x2, w2, bb)));
            float y = tanhf(z);
            float g = 1.f - y * y;
            float tg = 2.f * y * g;
            split_store(act, 0, p, j, y);
            split_store(act, 1, p, j, g * w0);
            split_store(act, 2, p, j, g * w1);
            split_store(act, 3, p, j, g * w2);
            split_store(act, 4, p, j, -tg * w0 * w0);
            split_store(act, 5, p, j, -tg * w1 * w1);
            split_store(act, 6, p, j, -tg * w2 * w2);
        }
    }
    __syncthreads();

    float acc[7][2][2][4];
#pragma unroll
    for (int c = 0; c < 7; c++)
#pragma unroll
        for (int a = 0; a < 2; a++)
#pragma unroll
            for (int bq = 0; bq < 2; bq++)
#pragma unroll
                for (int r = 0; r < 4; r++) acc[c][a][bq][r] = 0.f;

    for (int layer = 0; layer < 2; layer++) {
#pragma unroll 2
        for (int ks = 0; ks < 16; ks++) {
            uint4 ah[2], al[2];
#pragma unroll
            for (int jj = 0; jj < 2; jj++) {
                ah[jj] = g_aimg[aidx(layer, 0, wid * 2 + jj, ks, lane)];
                al[jj] = g_aimg[aidx(layer, 1, wid * 2 + jj, ks, lane)];
            }
#pragma unroll
            for (int ch = 0; ch < 7; ch++) {
                uint32_t bh[2][2], bl[2][2];
#pragma unroll
                for (int pt = 0; pt < 2; pt++)
#pragma unroll
                    for (int r = 0; r < 2; r++) {
                        int off = ch * 2 * PLANE + (pt * 8 + gid) * STRB +
                                  (ks * 16 + tig * 2 + r * 8) * 2;
                        bh[pt][r] = *(const uint32_t*)(act + off);
                        bl[pt][r] = *(const uint32_t*)(act + off + PLANE);
                    }
#pragma unroll
                for (int jj = 0; jj < 2; jj++)
#pragma unroll
                    for (int pt = 0; pt < 2; pt++) {
                        mma_bf16(acc[ch][jj][pt], (const uint32_t*)&ah[jj], bh[pt]);
                        mma_bf16(acc[ch][jj][pt], (const uint32_t*)&ah[jj], bl[pt]);
                        mma_bf16(acc[ch][jj][pt], (const uint32_t*)&al[jj], bh[pt]);
                    }
            }
        }
        __syncthreads();   // all b-frag reads done before act is overwritten

        if (layer == 0) {
#pragma unroll
            for (int jj = 0; jj < 2; jj++)
#pragma unroll
                for (int pt = 0; pt < 2; pt++)
#pragma unroll
                    for (int r = 0; r < 4; r++) {
                        int j = wid * 32 + jj * 16 + gid + ((r >> 1) << 3);
                        int p = pt * 8 + tig * 2 + (r & 1);
                        float zv = acc[0][jj][pt][r] + b2[j];
                        float y = tanhf(zv);
                        float g = 1.f - y * y;
                        float tg = 2.f * y * g;
                        split_store(act, 0, p, j, y);
#pragma unroll
                        for (int i = 0; i < 3; i++) {
                            float dz = acc[1 + i][jj][pt][r];
                            float sz = acc[4 + i][jj][pt][r];
                            split_store(act, 1 + i, p, j, g * dz);
                            split_store(act, 4 + i, p, j, fmaf(g, sz, -tg * dz * dz));
                        }
                    }
#pragma unroll
            for (int c = 0; c < 7; c++)
#pragma unroll
                for (int a = 0; a < 2; a++)
#pragma unroll
                    for (int bq = 0; bq < 2; bq++)
#pragma unroll
                        for (int r = 0; r < 4; r++) acc[c][a][bq][r] = 0.f;
            __syncthreads();
        } else {
            float us[2][2] = {{0.f, 0.f}, {0.f, 0.f}};
            float ls[2][2] = {{0.f, 0.f}, {0.f, 0.f}};
#pragma unroll
            for (int jj = 0; jj < 2; jj++)
#pragma unroll
                for (int pt = 0; pt < 2; pt++)
#pragma unroll
                    for (int r = 0; r < 4; r++) {
                        int j = wid * 32 + jj * 16 + gid + ((r >> 1) << 3);
                        float w4 = W4[j];
                        float zv = acc[0][jj][pt][r] + b3[j];
                        float y = tanhf(zv);
                        float g = 1.f - y * y;
                        float tg = 2.f * y * g;
                        float nsum = 0.f;
#pragma unroll
                        for (int i = 0; i < 3; i++) {
                            float dz = acc[1 + i][jj][pt][r];
                            float sz = acc[4 + i][jj][pt][r];
                            nsum += fmaf(g, sz, -tg * dz * dz);
                        }
                        us[pt][r & 1] = fmaf(y, w4, us[pt][r & 1]);
                        ls[pt][r & 1] = fmaf(nsum, w4, ls[pt][r & 1]);
                    }
            // reduce over gid (lanes with equal tig: xor 4, 8, 16)
#pragma unroll
            for (int off = 4; off <= 16; off <<= 1)
#pragma unroll
                for (int pt = 0; pt < 2; pt++)
#pragma unroll
                    for (int bq = 0; bq < 2; bq++) {
                        us[pt][bq] += __shfl_xor_sync(0xFFFFFFFFu, us[pt][bq], off);
                        ls[pt][bq] += __shfl_xor_sync(0xFFFFFFFFu, ls[pt][bq], off);
                    }
            if (gid == 0) {
#pragma unroll
                for (int pt = 0; pt < 2; pt++)
#pragma unroll
                    for (int bq = 0; bq < 2; bq++) {
                        int p = pt * 8 + tig * 2 + bq;
                        atomicAdd(&red[p], us[pt][bq]);
                        atomicAdd(&red[16 + p], ls[pt][bq]);
                    }
            }
        }
    }

    __syncthreads();
    if (wid == 0) {
        float rr = 0.f;
        if (lane < PTS && pt0 + lane < n) {
            float u = red[lane] + b4[0];
            float l = red[16 + lane];
            float r = l + k2 * u;
            rr = r * r;
        }
#pragma unroll
        for (int off = 16; off > 0; off >>= 1)
            rr += __shfl_xor_sync(0xFFFFFFFFu, rr, off);
        if (lane == 0) atomicAdd(&g_acc, (double)rr);
    }
}

__global__ void k_zero() { g_acc = 0.0; }
__global__ void k_fin(float* out, double inv_n) { out[0] = (float)(g_acc * inv_n); }

extern "C" void kernel_launch(void* const* d_in, const int* in_sizes, int n_in,
                              void* d_out, int out_size) {
    const float* inputs = (const float*)d_in[0];
    const float* W1 = (const float*)d_in[1];
    const float* b1 = (const float*)d_in[2];
    const float* W2 = (const float*)d_in[3];
    const float* b2 = (const float*)d_in[4];
    const float* W3 = (const float*)d_in[5];
    const float* b3 = (const float*)d_in[6];
    const float* W4 = (const float*)d_in[7];
    const float* b4 = (const float*)d_in[8];

    int n = in_sizes[0] / 3;
    const double C = 343.0;
    const double OMEGA = 2.0 * 3.14159265358979323846 * 1000.0;
    float k2 = (float)((C / OMEGA) * (C / OMEGA));

    cudaFuncSetAttribute(helm_hmma, cudaFuncAttributeMaxDynamicSharedMemorySize, SMEM_ALLOC);

    int blocks = (n + PTS - 1) / PTS;
    k_zero<<<1, 1>>>();
    prep_kernel<<<(2 * 2 * 16 * 16 * 32 + 255) / 256, 256>>>(W2, W3);
    helm_hmma<<<blocks, THREADS, SMEM_ALLOC>>>(inputs, W1, b1, b2, b3, W4, b4, n, k2);
    k_fin<<<1, 1>>>((float*)d_out, 1.0 / (double)n);
}

// round 10
// speedup vs baseline: 3.1003x; 1.6464x over previous
#include <cuda_runtime.h>
#include <cuda_bf16.h>
#include <math.h>
#include <stdint.h>

#define HID     256
#define PTS     8                 // points per CTA (one n8 mma tile)
#define THREADS 128               // 4 warps
#define NJJ     4                 // j-tiles (m16) per warp: 4 warps * 4 * 16 = 256 outputs
#define CHSTR   528               // bytes per (ks,ch) fragment block (512 + 16 pad)
#define OFF_RED (16 * 7 * CHSTR)  // 59136
#define OFF_INP (OFF_RED + 64)
#define SMEM_ALLOC (OFF_INP + 128)

__device__ double g_acc;
// Fragment-native A images: [layer][split][jt][ks][lane] -> uint4 (a0..a3)
__device__ uint4 g_aimg[2 * 2 * 16 * 16 * 32];

static __device__ __forceinline__ int aidx(int layer, int split, int jt, int ks, int lane) {
    return ((((layer * 2 + split) * 16 + jt) * 16 + ks) * 32) + lane;
}

__device__ __forceinline__ void mma_bf16(float* d, const uint32_t* a, const uint32_t* b) {
    asm volatile(
        "mma.sync.aligned.m16n8k16.row.col.f32.bf16.bf16.f32 "
        "{%0,%1,%2,%3},{%4,%5,%6,%7},{%8,%9},{%0,%1,%2,%3};"
        : "+f"(d[0]), "+f"(d[1]), "+f"(d[2]), "+f"(d[3])
        : "r"(a[0]), "r"(a[1]), "r"(a[2]), "r"(a[3]), "r"(b[0]), "r"(b[1]));
}

// Write hi/lo bf16 split of activation value v at (point p, input-dim j of next layer)
// directly into mma-b-fragment order: block (ks=j>>4, ch), lane = p*4+tig, 16B =
// [hi(k,k+1) | hi(k+8,k+9) | lo(k,k+1) | lo(k+8,k+9)]
__device__ __forceinline__ void frag_store(char* act, int ch, int p, int j, float v) {
    int ks = j >> 4, j16 = j & 15;
    int tig = (j16 >> 1) & 3, b1 = j16 >> 3, b0 = j16 & 1;
    char* base = act + (ks * 7 + ch) * CHSTR + (p * 4 + tig) * 16 + b1 * 4 + b0 * 2;
    __nv_bfloat16 hi = __float2bfloat16(v);
    __nv_bfloat16 lo = __float2bfloat16(v - __bfloat162float(hi));
    *(unsigned short*)base       = *(unsigned short*)&hi;
    *(unsigned short*)(base + 8) = *(unsigned short*)&lo;
}

// ============ prep: W2/W3 -> bf16 hi/lo mma A-fragment images (unchanged from R8) ============
__global__ void prep_kernel(const float* __restrict__ W2, const float* __restrict__ W3) {
    int e = blockIdx.x * blockDim.x + threadIdx.x;
    if (e >= 2 * 2 * 16 * 16 * 32) return;
    int lane = e & 31, ks = (e >> 5) & 15, jt = (e >> 9) & 15;
    int split = (e >> 13) & 1, layer = (e >> 14) & 1;
    const float* W = layer ? W3 : W2;
    int gid = lane >> 2, tig = lane & 3;
    uint32_t regs[4];
#pragma unroll
    for (int r = 0; r < 4; r++) {
        int j = jt * 16 + gid + ((r & 1) << 3);
        int k = ks * 16 + tig * 2 + ((r >> 1) << 3);
        float w0 = W[k * HID + j];
        float w1 = W[(k + 1) * HID + j];
        __nv_bfloat16 h0, h1;
        if (split == 0) {
            h0 = __float2bfloat16(w0);
            h1 = __float2bfloat16(w1);
        } else {
            __nv_bfloat16 t0 = __float2bfloat16(w0), t1 = __float2bfloat16(w1);
            h0 = __float2bfloat16(w0 - __bfloat162float(t0));
            h1 = __float2bfloat16(w1 - __bfloat162float(t1));
        }
        regs[r] = (uint32_t)*(unsigned short*)&h0 | ((uint32_t)*(unsigned short*)&h1 << 16);
    }
    g_aimg[e] = make_uint4(regs[0], regs[1], regs[2], regs[3]);
}

// ============ main kernel ============
__global__ void __launch_bounds__(THREADS, 2) helm_hmma(
    const float* __restrict__ inputs,
    const float* __restrict__ W1, const float* __restrict__ b1,
    const float* __restrict__ b2, const float* __restrict__ b3,
    const float* __restrict__ W4, const float* __restrict__ b4,
    int n, float k2) {

    extern __shared__ char act[];
    float* red = (float*)(act + OFF_RED);   // [8] u, [8] l
    float* inp = (float*)(act + OFF_INP);   // [8][3]

    int tid = threadIdx.x, wid = tid >> 5, lane = tid & 31;
    int gid = lane >> 2, tig = lane & 3;
    int pt0 = blockIdx.x * PTS;

    if (tid < 16) red[tid] = 0.f;
    if (tid < PTS * 3) {
        int p = tid / 3, c = tid % 3;
        inp[tid] = (pt0 + p < n) ? inputs[(pt0 + p) * 3 + c] : 0.f;
    }
    __syncthreads();

    // ---- Layer 1 (3 -> 256): thread handles j = tid and tid+128 ----
#pragma unroll
    for (int jh = 0; jh < 2; jh++) {
        int j = tid + jh * 128;
        float w0 = W1[j], w1 = W1[HID + j], w2 = W1[2 * HID + j], bb = b1[j];
#pragma unroll
        for (int p = 0; p < PTS; p++) {
            float x0 = inp[p * 3 + 0], x1 = inp[p * 3 + 1], x2 = inp[p * 3 + 2];
            float z = fmaf(x0, w0, fmaf(x1, w1, fmaf(x2, w2, bb)));
            float y = tanhf(z);
            float g = 1.f - y * y;
            float tg = 2.f * y * g;
            frag_store(act, 0, p, j, y);
            frag_store(act, 1, p, j, g * w0);
            frag_store(act, 2, p, j, g * w1);
            frag_store(act, 3, p, j, g * w2);
            frag_store(act, 4, p, j, -tg * w0 * w0);
            frag_store(act, 5, p, j, -tg * w1 * w1);
            frag_store(act, 6, p, j, -tg * w2 * w2);
        }
    }
    __syncthreads();

    float acc[7][NJJ][4];
    float us[2] = {0.f, 0.f}, ls[2] = {0.f, 0.f};

    for (int layer = 0; layer < 2; layer++) {
#pragma unroll
        for (int c = 0; c < 7; c++)
#pragma unroll
            for (int jj = 0; jj < NJJ; jj++)
#pragma unroll
                for (int r = 0; r < 4; r++) acc[c][jj][r] = 0.f;

        // ---- GEMM: software-pipelined A-fragment loads ----
        uint4 ah[NJJ], al[NJJ], ahn[NJJ], aln[NJJ];
#pragma unroll
        for (int jj = 0; jj < NJJ; jj++) {
            ah[jj] = g_aimg[aidx(layer, 0, wid * NJJ + jj, 0, lane)];
            al[jj] = g_aimg[aidx(layer, 1, wid * NJJ + jj, 0, lane)];
        }
        for (int ks = 0; ks < 16; ks++) {
            int ksn = (ks < 15) ? ks + 1 : 15;
#pragma unroll
            for (int jj = 0; jj < NJJ; jj++) {
                ahn[jj] = g_aimg[aidx(layer, 0, wid * NJJ + jj, ksn, lane)];
                aln[jj] = g_aimg[aidx(layer, 1, wid * NJJ + jj, ksn, lane)];
            }
#pragma unroll
            for (int ch = 0; ch < 7; ch++) {
                uint4 bf = *(const uint4*)(act + (ks * 7 + ch) * CHSTR + lane * 16);
                uint32_t bh[2] = {bf.x, bf.y}, bl[2] = {bf.z, bf.w};
#pragma unroll
                for (int jj = 0; jj < NJJ; jj++) {
                    mma_bf16(acc[ch][jj], (const uint32_t*)&ah[jj], bh);
                    mma_bf16(acc[ch][jj], (const uint32_t*)&ah[jj], bl);
                    mma_bf16(acc[ch][jj], (const uint32_t*)&al[jj], bh);
                }
            }
#pragma unroll
            for (int jj = 0; jj < NJJ; jj++) { ah[jj] = ahn[jj]; al[jj] = aln[jj]; }
        }
        __syncthreads();   // all fragment reads done before act is overwritten

        if (layer == 0) {
#pragma unroll
            for (int jj = 0; jj < NJJ; jj++)
#pragma unroll
                for (int r = 0; r < 4; r++) {
                    int j = (wid * NJJ + jj) * 16 + gid + ((r >> 1) << 3);
                    int p = tig * 2 + (r & 1);
                    float zv = acc[0][jj][r] + b2[j];
                    float y = tanhf(zv);
                    float g = 1.f - y * y;
                    float tg = 2.f * y * g;
                    frag_store(act, 0, p, j, y);
#pragma unroll
                    for (int i = 0; i < 3; i++) {
                        float dz = acc[1 + i][jj][r];
                        float sz = acc[4 + i][jj][r];
                        frag_store(act, 1 + i, p, j, g * dz);
                        frag_store(act, 4 + i, p, j, fmaf(g, sz, -tg * dz * dz));
                    }
                }
            __syncthreads();
        } else {
#pragma unroll
            for (int jj = 0; jj < NJJ; jj++)
#pragma unroll
                for (int r = 0; r < 4; r++) {
                    int j = (wid * NJJ + jj) * 16 + gid + ((r >> 1) << 3);
                    float w4 = W4[j];
                    float zv = acc[0][jj][r] + b3[j];
                    float y = tanhf(zv);
                    float g = 1.f - y * y;
                    float tg = 2.f * y * g;
                    float nsum = 0.f;
#pragma unroll
                    for (int i = 0; i < 3; i++) {
                        float dz = acc[1 + i][jj][r];
                        float sz = acc[4 + i][jj][r];
                        nsum += fmaf(g, sz, -tg * dz * dz);
                    }
                    us[r & 1] = fmaf(y, w4, us[r & 1]);
                    ls[r & 1] = fmaf(nsum, w4, ls[r & 1]);
                }
        }
    }

    // reduce over gid (lane bits 2..4); survivors: lanes 0..3 (tig), b0 in index
#pragma unroll
    for (int off = 4; off <= 16; off <<= 1)
#pragma unroll
        for (int b0 = 0; b0 < 2; b0++) {
            us[b0] += __shfl_xor_sync(0xFFFFFFFFu, us[b0], off);
            ls[b0] += __shfl_xor_sync(0xFFFFFFFFu, ls[b0], off);
        }
    if (gid == 0) {
#pragma unroll
        for (int b0 = 0; b0 < 2; b0++) {
            int p = tig * 2 + b0;
            atomicAdd(&red[p], us[b0]);
            atomicAdd(&red[8 + p], ls[b0]);
        }
    }

    __syncthreads();
    if (wid == 0) {
        float rr = 0.f;
        if (lane < PTS && pt0 + lane < n) {
            float u = red[lane] + b4[0];
            float l = red[8 + lane];
            float r = l + k2 * u;
            rr = r * r;
        }
#pragma unroll
        for (int off = 16; off > 0; off >>= 1)
            rr += __shfl_xor_sync(0xFFFFFFFFu, rr, off);
        if (lane == 0) atomicAdd(&g_acc, (double)rr);
    }
}

__global__ void k_zero() { g_acc = 0.0; }
__global__ void k_fin(float* out, double inv_n) { out[0] = (float)(g_acc * inv_n); }

extern "C" void kernel_launch(void* const* d_in, const int* in_sizes, int n_in,
                              void* d_out, int out_size) {
    const float* inputs = (const float*)d_in[0];
    const float* W1 = (const float*)d_in[1];
    const float* b1 = (const float*)d_in[2];
    const float* W2 = (const float*)d_in[3];
    const float* b2 = (const float*)d_in[4];
    const float* W3 = (const float*)d_in[5];
    const float* b3 = (const float*)d_in[6];
    const float* W4 = (const float*)d_in[7];
    const float* b4 = (const float*)d_in[8];

    int n = in_sizes[0] / 3;
    const double C = 343.0;
    const double OMEGA = 2.0 * 3.14159265358979323846 * 1000.0;
    float k2 = (float)((C / OMEGA) * (C / OMEGA));

    cudaFuncSetAttribute(helm_hmma, cudaFuncAttributeMaxDynamicSharedMemorySize, SMEM_ALLOC);

    int blocks = (n + PTS - 1) / PTS;
    k_zero<<<1, 1>>>();
    prep_kernel<<<(2 * 2 * 16 * 16 * 32 + 255) / 256, 256>>>(W2, W3);
    helm_hmma<<<blocks, THREADS, SMEM_ALLOC>>>(inputs, W1, b1, b2, b3, W4, b4, n, k2);
    k_fin<<<1, 1>>>((float*)d_out, 1.0 / (double)n);
}

// round 11
// speedup vs baseline: 5.5739x; 1.7979x over previous
#include <cuda_runtime.h>
#include <cuda_fp16.h>
#include <math.h>
#include <stdint.h>

#define HID     256
#define PTS     16                // points per CTA (2 n8 mma tiles)
#define THREADS 128               // 4 warps
#define NJJ     4                 // j-tiles (m16) per warp: 4 warps * 4 * 16 = 256 outputs
#define NT      2                 // n8 tiles
#define NCH     5                 // value, d0, d1, d2, laplacian
#define CHB     528               // bytes per (ks,ch,nt) fragment block (512 + 16 pad)
#define FRAG_OFF(ks,ch,nt) ((((ks)*NCH+(ch))*2+(nt))*CHB)
#define OFF_RED (16 * NCH * 2 * CHB)   // 84480
#define OFF_INP (OFF_RED + 128)
#define SMEM_ALLOC (OFF_INP + 192)

__device__ double g_acc;
// fp16 hi-split A-fragment images: [layer][jt][ks][lane] -> uint4 (a0..a3)
__device__ uint4 g_aimg[2 * 16 * 16 * 32];

static __device__ __forceinline__ int aidx(int layer, int jt, int ks, int lane) {
    return (((layer * 16 + jt) * 16 + ks) * 32) + lane;
}

__device__ __forceinline__ void mma_f16(float* d, const uint32_t* a, const uint32_t* b) {
    asm volatile(
        "mma.sync.aligned.m16n8k16.row.col.f32.f16.f16.f32 "
        "{%0,%1,%2,%3},{%4,%5,%6,%7},{%8,%9},{%0,%1,%2,%3};"
        : "+f"(d[0]), "+f"(d[1]), "+f"(d[2]), "+f"(d[3])
        : "r"(a[0]), "r"(a[1]), "r"(a[2]), "r"(a[3]), "r"(b[0]), "r"(b[1]));
}

// fp16 hi/lo split of activation v at (point p, next-layer input dim j),
// written directly in mma B-fragment order.
__device__ __forceinline__ void frag_store(char* act, int ch, int p, int j, float v) {
    int ks = j >> 4, j16 = j & 15;
    int tk = (j16 >> 1) & 3, b1 = j16 >> 3, b0 = j16 & 1;
    int nt = p >> 3, p8 = p & 7;
    char* base = act + FRAG_OFF(ks, ch, nt) + (p8 * 4 + tk) * 16 + b1 * 4 + b0 * 2;
    __half hi = __float2half_rn(v);
    __half lo = __float2half_rn(v - __half2float(hi));
    *(unsigned short*)base       = *(unsigned short*)&hi;
    *(unsigned short*)(base + 8) = *(unsigned short*)&lo;
}

// ============ prep: W2/W3 -> fp16 hi mma A-fragment images ============
__global__ void prep_kernel(const float* __restrict__ W2, const float* __restrict__ W3) {
    int e = blockIdx.x * blockDim.x + threadIdx.x;
    if (e >= 2 * 16 * 16 * 32) return;
    int lane = e & 31, ks = (e >> 5) & 15, jt = (e >> 9) & 15, layer = (e >> 13) & 1;
    const float* W = layer ? W3 : W2;
    int gid = lane >> 2, tig = lane & 3;
    uint32_t regs[4];
#pragma unroll
    for (int r = 0; r < 4; r++) {
        int j = jt * 16 + gid + ((r & 1) << 3);
        int k = ks * 16 + tig * 2 + ((r >> 1) << 3);
        __half h0 = __float2half_rn(W[k * HID + j]);
        __half h1 = __float2half_rn(W[(k + 1) * HID + j]);
        regs[r] = (uint32_t)*(unsigned short*)&h0 | ((uint32_t)*(unsigned short*)&h1 << 16);
    }
    g_aimg[e] = make_uint4(regs[0], regs[1], regs[2], regs[3]);
}

// ============ main kernel ============
__global__ void __launch_bounds__(THREADS, 2) helm_hmma(
    const float* __restrict__ inputs,
    const float* __restrict__ W1, const float* __restrict__ b1,
    const float* __restrict__ b2, const float* __restrict__ b3,
    const float* __restrict__ W4, const float* __restrict__ b4,
    int n, float k2) {

    extern __shared__ char act[];
    float* red = (float*)(act + OFF_RED);   // [16] u, [16] l
    float* inp = (float*)(act + OFF_INP);   // [16][3]

    int tid = threadIdx.x, wid = tid >> 5, lane = tid & 31;
    int gid = lane >> 2, tig = lane & 3;
    int pt0 = blockIdx.x * PTS;

    if (tid < 32) red[tid] = 0.f;
    if (tid < PTS * 3) {
        int p = tid / 3, c = tid % 3;
        inp[tid] = (pt0 + p < n) ? inputs[(pt0 + p) * 3 + c] : 0.f;
    }
    __syncthreads();

    // ---- Layer 1 (3 -> 256): thread handles j = tid and tid+128 ----
#pragma unroll
    for (int jh = 0; jh < 2; jh++) {
        int j = tid + jh * 128;
        float w0 = W1[j], w1 = W1[HID + j], w2 = W1[2 * HID + j], bb = b1[j];
        float wss = w0 * w0 + w1 * w1 + w2 * w2;
#pragma unroll
        for (int p = 0; p < PTS; p++) {
            float x0 = inp[p * 3 + 0], x1 = inp[p * 3 + 1], x2 = inp[p * 3 + 2];
            float z = fmaf(x0, w0, fmaf(x1, w1, fmaf(x2, w2, bb)));
            float y = tanhf(z);
            float g = 1.f - y * y;
            float tg = 2.f * y * g;
            frag_store(act, 0, p, j, y);
            frag_store(act, 1, p, j, g * w0);
            frag_store(act, 2, p, j, g * w1);
            frag_store(act, 3, p, j, g * w2);
            frag_store(act, 4, p, j, -tg * wss);       // laplacian channel
        }
    }
    __syncthreads();

    float acc[NCH][NJJ][NT][4];
    float us[NT][2], ls[NT][2];
#pragma unroll
    for (int nt = 0; nt < NT; nt++)
#pragma unroll
        for (int b0 = 0; b0 < 2; b0++) { us[nt][b0] = 0.f; ls[nt][b0] = 0.f; }

    for (int layer = 0; layer < 2; layer++) {
#pragma unroll
        for (int c = 0; c < NCH; c++)
#pragma unroll
            for (int jj = 0; jj < NJJ; jj++)
#pragma unroll
                for (int nt = 0; nt < NT; nt++)
#pragma unroll
                    for (int r = 0; r < 4; r++) acc[c][jj][nt][r] = 0.f;

        // ---- GEMM: 2-pass fp16 (ah*bh + ah*bl), A prefetch pipelined ----
        uint4 ah[NJJ], ahn[NJJ];
#pragma unroll
        for (int jj = 0; jj < NJJ; jj++)
            ah[jj] = g_aimg[aidx(layer, wid * NJJ + jj, 0, lane)];
        for (int ks = 0; ks < 16; ks++) {
            int ksn = (ks < 15) ? ks + 1 : 15;
#pragma unroll
            for (int jj = 0; jj < NJJ; jj++)
                ahn[jj] = g_aimg[aidx(layer, wid * NJJ + jj, ksn, lane)];
#pragma unroll
            for (int ch = 0; ch < NCH; ch++)
#pragma unroll
                for (int nt = 0; nt < NT; nt++) {
                    uint4 bf = *(const uint4*)(act + FRAG_OFF(ks, ch, nt) + lane * 16);
                    uint32_t bh[2] = {bf.x, bf.y}, bl[2] = {bf.z, bf.w};
#pragma unroll
                    for (int jj = 0; jj < NJJ; jj++) {
                        mma_f16(acc[ch][jj][nt], (const uint32_t*)&ah[jj], bh);
                        mma_f16(acc[ch][jj][nt], (const uint32_t*)&ah[jj], bl);
                    }
                }
#pragma unroll
            for (int jj = 0; jj < NJJ; jj++) ah[jj] = ahn[jj];
        }
        __syncthreads();   // all fragment reads done before act is overwritten

        if (layer == 0) {
#pragma unroll
            for (int jj = 0; jj < NJJ; jj++)
#pragma unroll
                for (int nt = 0; nt < NT; nt++)
#pragma unroll
                    for (int r = 0; r < 4; r++) {
                        int j = (wid * NJJ + jj) * 16 + gid + ((r >> 1) << 3);
                        int p = nt * 8 + tig * 2 + (r & 1);
                        float zv = acc[0][jj][nt][r] + b2[j];
                        float y = tanhf(zv);
                        float g = 1.f - y * y;
                        float tg = 2.f * y * g;
                        float zd0 = acc[1][jj][nt][r];
                        float zd1 = acc[2][jj][nt][r];
                        float zd2 = acc[3][jj][nt][r];
                        float zl  = acc[4][jj][nt][r];
                        frag_store(act, 0, p, j, y);
                        frag_store(act, 1, p, j, g * zd0);
                        frag_store(act, 2, p, j, g * zd1);
                        frag_store(act, 3, p, j, g * zd2);
                        float dsq = fmaf(zd0, zd0, fmaf(zd1, zd1, zd2 * zd2));
                        frag_store(act, 4, p, j, fmaf(g, zl, -tg * dsq));
                    }
            __syncthreads();
        } else {
#pragma unroll
            for (int jj = 0; jj < NJJ; jj++)
#pragma unroll
                for (int nt = 0; nt < NT; nt++)
#pragma unroll
                    for (int r = 0; r < 4; r++) {
                        int j = (wid * NJJ + jj) * 16 + gid + ((r >> 1) << 3);
                        float w4 = W4[j];
                        float zv = acc[0][jj][nt][r] + b3[j];
                        float y = tanhf(zv);
                        float g = 1.f - y * y;
                        float tg = 2.f * y * g;
                        float zd0 = acc[1][jj][nt][r];
                        float zd1 = acc[2][jj][nt][r];
                        float zd2 = acc[3][jj][nt][r];
                        float zl  = acc[4][jj][nt][r];
                        float dsq = fmaf(zd0, zd0, fmaf(zd1, zd1, zd2 * zd2));
                        float lap = fmaf(g, zl, -tg * dsq);
                        us[nt][r & 1] = fmaf(y, w4, us[nt][r & 1]);
                        ls[nt][r & 1] = fmaf(lap, w4, ls[nt][r & 1]);
                    }
        }
    }

    // reduce over gid (lane bits 2..4); survivors lanes 0..3 (tig)
#pragma unroll
    for (int off = 4; off <= 16; off <<= 1)
#pragma unroll
        for (int nt = 0; nt < NT; nt++)
#pragma unroll
            for (int b0 = 0; b0 < 2; b0++) {
                us[nt][b0] += __shfl_xor_sync(0xFFFFFFFFu, us[nt][b0], off);
                ls[nt][b0] += __shfl_xor_sync(0xFFFFFFFFu, ls[nt][b0], off);
            }
    if (gid == 0) {
#pragma unroll
        for (int nt = 0; nt < NT; nt++)
#pragma unroll
            for (int b0 = 0; b0 < 2; b0++) {
                int p = nt * 8 + tig * 2 + b0;
                atomicAdd(&red[p], us[nt][b0]);
                atomicAdd(&red[16 + p], ls[nt][b0]);
            }
    }

    __syncthreads();
    if (wid == 0) {
        float rr = 0.f;
        if (lane < PTS && pt0 + lane < n) {
            float u = red[lane] + b4[0];
            float l = red[16 + lane];
            float r = l + k2 * u;
            rr = r * r;
        }
#pragma unroll
        for (int off = 16; off > 0; off >>= 1)
            rr += __shfl_xor_sync(0xFFFFFFFFu, rr, off);
        if (lane == 0) atomicAdd(&g_acc, (double)rr);
    }
}

__global__ void k_zero() { g_acc = 0.0; }
__global__ void k_fin(float* out, double inv_n) { out[0] = (float)(g_acc * inv_n); }

extern "C" void kernel_launch(void* const* d_in, const int* in_sizes, int n_in,
                              void* d_out, int out_size) {
    const float* inputs = (const float*)d_in[0];
    const float* W1 = (const float*)d_in[1];
    const float* b1 = (const float*)d_in[2];
    const float* W2 = (const float*)d_in[3];
    const float* b2 = (const float*)d_in[4];
    const float* W3 = (const float*)d_in[5];
    const float* b3 = (const float*)d_in[6];
    const float* W4 = (const float*)d_in[7];
    const float* b4 = (const float*)d_in[8];

    int n = in_sizes[0] / 3;
    const double C = 343.0;
    const double OMEGA = 2.0 * 3.14159265358979323846 * 1000.0;
    float k2 = (float)((C / OMEGA) * (C / OMEGA));

    cudaFuncSetAttribute(helm_hmma, cudaFuncAttributeMaxDynamicSharedMemorySize, SMEM_ALLOC);

    int blocks = (n + PTS - 1) / PTS;
    k_zero<<<1, 1>>>();
    prep_kernel<<<(2 * 16 * 16 * 32 + 255) / 256, 256>>>(W2, W3);
    helm_hmma<<<blocks, THREADS, SMEM_ALLOC>>>(inputs, W1, b1, b2, b3, W4, b4, n, k2);
    k_fin<<<1, 1>>>((float*)d_out, 1.0 / (double)n);
}